// round 6
// baseline (speedup 1.0000x reference)
#include <cuda_runtime.h>
#include <cuda_bf16.h>

#define LNUM 2
#define BB 64
#define TSTEPS 512
#define DIN 512
#define HD 512
#define PD 256
#define OD 512
#define NBLK 148
#define NTHR 256

// ----------------- persistent device state (no allocations) -----------------
__device__ float g_h[LNUM][BB * HD];   // hidden state (h_mem) per layer
__device__ float g_m[LNUM][BB * PD];   // memory state per layer
__device__ float g_rh[BB * HD];        // sigma(r) * h_old
__device__ float g_us[BB * HD];        // sigma(u)
__device__ float g_hc[BB * HD];        // h_cand
__device__ float g_mo[BB * PD];        // read_gate * m
__device__ float g_wg[4][BB * PD];     // write-gate pre-activations: mw, mu, d, s
__device__ unsigned g_count;           // barrier arrival counter (self-resetting)
__device__ unsigned g_gen;             // barrier generation (monotonic)

struct Params {
    const float *x, *Wr, *br, *Wu, *bu, *Wn, *bn, *Wmr, *bmr, *Wmw, *bmw,
                *Wmu, *bmu, *Wmh, *bmh, *Wd, *bd, *Ws, *bs, *Wout, *bout,
                *dop, *ser;
    float* out;
    long long out_size;
};

__device__ __forceinline__ float sigf(float v) { return 1.f / (1.f + __expf(-v)); }
__device__ __forceinline__ float tanhf_(float v) {
    float e = __expf(-2.f * fabsf(v));
    float r = (1.f - e) / (1.f + e);
    return v < 0.f ? -r : r;
}

// Sense-reversing grid barrier: counter resets each use; generation monotonic,
// so state is consistent across graph replays. All 148 blocks are co-resident.
__device__ __forceinline__ void gridbar() {
    __syncthreads();
    if (threadIdx.x == 0) {
        __threadfence();  // release
        unsigned gen = *(volatile unsigned*)&g_gen;
        unsigned a = atomicAdd(&g_count, 1u);
        if (a == NBLK - 1) {
            atomicExch(&g_count, 0u);
            __threadfence();
            atomicAdd(&g_gen, 1u);
        } else {
            while (*(volatile unsigned*)&g_gen == gen) __nanosleep(64);
        }
        __threadfence();  // acquire
    }
    __syncthreads();
}

struct alignas(16) SM {
    float A[2][32 * 65];  // A chunk: [k][row], pad 65 -> conflict free
    float W[2][32 * 8];   // W chunk: [k][col]
};

// out[64, 8] (cols col0..col0+7) = A[64, Ktot] * W[8, Ktot]^T
// A is a concat: rows use A1 for k < K1, A2 for k >= K1 (chunks never straddle).
// Thread map: row = tid&63, colpair = (tid>>6)*2. Register-staged double buffer.
__device__ __forceinline__ void gemm8(
    SM& sm,
    const float* __restrict__ A1, int lda1, int K1,
    const float* __restrict__ A2, int lda2, int Ktot,
    const float* __restrict__ Wp, int wld, float acc[2])
{
    const int tid = threadIdx.x;
    const int kq = tid & 31;
    const int rq = tid >> 5;       // 0..7
    const int row = tid & 63;
    const int g2 = (tid >> 6) * 2; // 0,2,4,6
    float ra[8];
    float rw;
    const int nch = Ktot >> 5;
    acc[0] = 0.f; acc[1] = 0.f;

    // prologue: load chunk 0
    {
        const float* Ap = A1; int lda = lda1;
#pragma unroll
        for (int i = 0; i < 8; i++) ra[i] = Ap[(rq + 8 * i) * lda + kq];
        rw = Wp[rq * wld + kq];
    }
#pragma unroll
    for (int i = 0; i < 8; i++) sm.A[0][kq * 65 + rq + 8 * i] = ra[i];
    sm.W[0][kq * 8 + rq] = rw;

    for (int ch = 0; ch < nch; ch++) {
        __syncthreads();
        const bool more = (ch + 1 < nch);
        if (more) {
            int kk = (ch + 1) << 5;
            const float* Ap; int lda; int ko;
            if (kk < K1) { Ap = A1; lda = lda1; ko = kk; }
            else         { Ap = A2; lda = lda2; ko = kk - K1; }
#pragma unroll
            for (int i = 0; i < 8; i++) ra[i] = Ap[(rq + 8 * i) * lda + ko + kq];
            rw = Wp[rq * wld + kk + kq];
        }
        const int b = ch & 1;
        const float* as = &sm.A[b][row];
        const float* ws = &sm.W[b][g2];
#pragma unroll
        for (int k = 0; k < 32; k++) {
            float a = as[k * 65];
            float2 w = *(const float2*)(ws + k * 8);
            acc[0] = fmaf(a, w.x, acc[0]);
            acc[1] = fmaf(a, w.y, acc[1]);
        }
        if (more) {
            const int nb = b ^ 1;
#pragma unroll
            for (int i = 0; i < 8; i++) sm.A[nb][kq * 65 + rq + 8 * i] = ra[i];
            sm.W[nb][kq * 8 + rq] = rw;
        }
    }
    __syncthreads();
}

__global__ void __launch_bounds__(NTHR, 1)
gru_kernel(Params pr)
{
    __shared__ SM sm;
    const int tid = threadIdx.x;
    const int row = tid & 63;
    const int g2 = (tid >> 6) * 2;

    const float dopa = pr.dop[0];
    const float sero = pr.ser[0];

    // init: zero recurrent state
    {
        float* hp = &g_h[0][0];
        for (int i = blockIdx.x * NTHR + tid; i < LNUM * BB * HD; i += NBLK * NTHR)
            hp[i] = 0.f;
        float* mp = &g_m[0][0];
        for (int i = blockIdx.x * NTHR + tid; i < LNUM * BB * PD; i += NBLK * NTHR)
            mp[i] = 0.f;
    }
    gridbar();

    for (int t = 0; t < TSTEPS; t++) {
        const float* xt = pr.x + (size_t)t * DIN;  // row stride TSTEPS*DIN

        // ---- P1: r0, u0  (+ out(t-1), layer-1 write gates(t-1)) ----
        {
            int nt = (t > 0) ? 320 : 128;
            for (int tile = blockIdx.x; tile < nt; tile += NBLK) {
                float acc[2];
                if (tile < 64) {  // r0
                    int c0 = tile * 8;
                    gemm8(sm, xt, TSTEPS * DIN, DIN, g_h[0], HD, DIN + HD,
                          pr.Wr + (size_t)c0 * (DIN + HD), DIN + HD, acc);
                    int c = c0 + g2;
#pragma unroll
                    for (int j = 0; j < 2; j++) {
                        float v = sigf(acc[j] + pr.br[c + j]);
                        int idx = row * HD + c + j;
                        g_rh[idx] = v * g_h[0][idx];
                    }
                } else if (tile < 128) {  // u0
                    int c0 = (tile - 64) * 8;
                    gemm8(sm, xt, TSTEPS * DIN, DIN, g_h[0], HD, DIN + HD,
                          pr.Wu + (size_t)c0 * (DIN + HD), DIN + HD, acc);
                    int c = c0 + g2;
#pragma unroll
                    for (int j = 0; j < 2; j++)
                        g_us[row * HD + c + j] = sigf(acc[j] + pr.bu[c + j]);
                } else if (tile < 192) {  // out(t-1) from h_mem layer 1
                    int c0 = (tile - 128) * 8;
                    gemm8(sm, g_h[1], HD, HD, g_h[1], HD, HD,
                          pr.Wout + (size_t)c0 * HD, HD, acc);
                    int c = c0 + g2;
#pragma unroll
                    for (int j = 0; j < 2; j++)
                        pr.out[(size_t)row * TSTEPS * OD + (size_t)(t - 1) * OD + c + j]
                            = acc[j] + pr.bout[c + j];
                } else {  // layer-1 write gates from h_mem layer 1 (step t-1)
                    int q = tile - 192;
                    int gi = q >> 5;
                    int c0 = (q & 31) * 8;
                    const float* Wg = (gi == 0) ? pr.Wmw : (gi == 1) ? pr.Wmu
                                    : (gi == 2) ? pr.Wd : pr.Ws;
                    const float* bg = (gi == 0) ? pr.bmw : (gi == 1) ? pr.bmu
                                    : (gi == 2) ? pr.bd : pr.bs;
                    gemm8(sm, g_h[1], HD, HD, g_h[1], HD, HD,
                          Wg + (size_t)(PD + c0) * HD, HD, acc);
                    int c = c0 + g2;
#pragma unroll
                    for (int j = 0; j < 2; j++)
                        g_wg[gi][row * PD + c + j] = acc[j] + bg[PD + c + j];
                }
            }
        }
        gridbar();

        // ---- P2: n0 (+ combine layer-1 memory update from t-1) ----
        {
            int nt = (t > 0) ? 72 : 64;
            for (int tile = blockIdx.x; tile < nt; tile += NBLK) {
                if (tile < 64) {
                    float acc[2];
                    int c0 = tile * 8;
                    gemm8(sm, xt, TSTEPS * DIN, DIN, g_rh, HD, DIN + HD,
                          pr.Wn + (size_t)c0 * (DIN + HD), DIN + HD, acc);
                    int c = c0 + g2;
#pragma unroll
                    for (int j = 0; j < 2; j++) {
                        float nh = tanhf_(acc[j] + pr.bn[c + j]);
                        int idx = row * HD + c + j;
                        float u_ = g_us[idx];
                        g_hc[idx] = (1.f - u_) * g_h[0][idx] + u_ * nh;
                    }
                } else {  // combine m[1]
                    int e0 = (tile - 64) * 2048;
#pragma unroll
                    for (int j = 0; j < 8; j++) {
                        int e = e0 + tid + j * 256;
                        float w = sigf(g_wg[0][e]) * sigf(g_wg[2][e] * dopa)
                                  * (1.f - sigf(g_wg[3][e] * sero));
                        g_m[1][e] = (1.f - w) * g_m[1][e] + w * tanhf_(g_wg[1][e]);
                    }
                }
            }
        }
        gridbar();

        // ---- P3: read gate layer 0 ----
        for (int tile = blockIdx.x; tile < 32; tile += NBLK) {
            float acc[2];
            int c0 = tile * 8;
            gemm8(sm, g_hc, HD, HD, g_hc, HD, HD, pr.Wmr + (size_t)c0 * HD, HD, acc);
            int c = c0 + g2;
#pragma unroll
            for (int j = 0; j < 2; j++) {
                float rg = sigf(acc[j] + pr.bmr[c + j]);
                int idx = row * PD + c + j;
                g_mo[idx] = rg * g_m[0][idx];
            }
        }
        gridbar();

        // ---- P4: h_mem layer 0 = h_cand + mem_out*Wmh^T + bmh ----
        for (int tile = blockIdx.x; tile < 64; tile += NBLK) {
            float acc[2];
            int c0 = tile * 8;
            gemm8(sm, g_mo, PD, PD, g_mo, PD, PD, pr.Wmh + (size_t)c0 * PD, PD, acc);
            int c = c0 + g2;
#pragma unroll
            for (int j = 0; j < 2; j++) {
                int idx = row * HD + c + j;
                g_h[0][idx] = g_hc[idx] + acc[j] + pr.bmh[c + j];
            }
        }
        gridbar();

        // ---- P5: r1, u1 (+ layer-0 write gates) ----
        for (int tile = blockIdx.x; tile < 256; tile += NBLK) {
            float acc[2];
            if (tile < 64) {  // r1
                int c0 = tile * 8;
                gemm8(sm, g_h[0], HD, HD, g_h[1], HD, DIN + HD,
                      pr.Wr + (size_t)(HD + c0) * (DIN + HD), DIN + HD, acc);
                int c = c0 + g2;
#pragma unroll
                for (int j = 0; j < 2; j++) {
                    float v = sigf(acc[j] + pr.br[HD + c + j]);
                    int idx = row * HD + c + j;
                    g_rh[idx] = v * g_h[1][idx];
                }
            } else if (tile < 128) {  // u1
                int c0 = (tile - 64) * 8;
                gemm8(sm, g_h[0], HD, HD, g_h[1], HD, DIN + HD,
                      pr.Wu + (size_t)(HD + c0) * (DIN + HD), DIN + HD, acc);
                int c = c0 + g2;
#pragma unroll
                for (int j = 0; j < 2; j++)
                    g_us[row * HD + c + j] = sigf(acc[j] + pr.bu[HD + c + j]);
            } else {  // layer-0 write gates from h_mem layer 0
                int q = tile - 128;
                int gi = q >> 5;
                int c0 = (q & 31) * 8;
                const float* Wg = (gi == 0) ? pr.Wmw : (gi == 1) ? pr.Wmu
                                : (gi == 2) ? pr.Wd : pr.Ws;
                const float* bg = (gi == 0) ? pr.bmw : (gi == 1) ? pr.bmu
                                : (gi == 2) ? pr.bd : pr.bs;
                gemm8(sm, g_h[0], HD, HD, g_h[0], HD, HD,
                      Wg + (size_t)c0 * HD, HD, acc);
                int c = c0 + g2;
#pragma unroll
                for (int j = 0; j < 2; j++)
                    g_wg[gi][row * PD + c + j] = acc[j] + bg[c + j];
            }
        }
        gridbar();

        // ---- P6: n1 (+ combine layer-0 memory update) ----
        for (int tile = blockIdx.x; tile < 72; tile += NBLK) {
            if (tile < 64) {
                float acc[2];
                int c0 = tile * 8;
                gemm8(sm, g_h[0], HD, HD, g_rh, HD, DIN + HD,
                      pr.Wn + (size_t)(HD + c0) * (DIN + HD), DIN + HD, acc);
                int c = c0 + g2;
#pragma unroll
                for (int j = 0; j < 2; j++) {
                    float nh = tanhf_(acc[j] + pr.bn[HD + c + j]);
                    int idx = row * HD + c + j;
                    float u_ = g_us[idx];
                    g_hc[idx] = (1.f - u_) * g_h[1][idx] + u_ * nh;
                }
            } else {  // combine m[0]
                int e0 = (tile - 64) * 2048;
#pragma unroll
                for (int j = 0; j < 8; j++) {
                    int e = e0 + tid + j * 256;
                    float w = sigf(g_wg[0][e]) * sigf(g_wg[2][e] * dopa)
                              * (1.f - sigf(g_wg[3][e] * sero));
                    g_m[0][e] = (1.f - w) * g_m[0][e] + w * tanhf_(g_wg[1][e]);
                }
            }
        }
        gridbar();

        // ---- P7: read gate layer 1 ----
        for (int tile = blockIdx.x; tile < 32; tile += NBLK) {
            float acc[2];
            int c0 = tile * 8;
            gemm8(sm, g_hc, HD, HD, g_hc, HD, HD,
                  pr.Wmr + (size_t)(PD + c0) * HD, HD, acc);
            int c = c0 + g2;
#pragma unroll
            for (int j = 0; j < 2; j++) {
                float rg = sigf(acc[j] + pr.bmr[PD + c + j]);
                int idx = row * PD + c + j;
                g_mo[idx] = rg * g_m[1][idx];
            }
        }
        gridbar();

        // ---- P8: h_mem layer 1 ----
        for (int tile = blockIdx.x; tile < 64; tile += NBLK) {
            float acc[2];
            int c0 = tile * 8;
            gemm8(sm, g_mo, PD, PD, g_mo, PD, PD,
                  pr.Wmh + (size_t)(HD + c0) * PD, PD, acc);
            int c = c0 + g2;
#pragma unroll
            for (int j = 0; j < 2; j++) {
                int idx = row * HD + c + j;
                g_h[1][idx] = g_hc[idx] + acc[j] + pr.bmh[HD + c + j];
            }
        }
        gridbar();
    }

    // ---- PF1: out(T-1) + layer-1 write gates of last step ----
    for (int tile = blockIdx.x; tile < 192; tile += NBLK) {
        float acc[2];
        if (tile < 64) {
            int c0 = tile * 8;
            gemm8(sm, g_h[1], HD, HD, g_h[1], HD, HD,
                  pr.Wout + (size_t)c0 * HD, HD, acc);
            int c = c0 + g2;
#pragma unroll
            for (int j = 0; j < 2; j++)
                pr.out[(size_t)row * TSTEPS * OD + (size_t)(TSTEPS - 1) * OD + c + j]
                    = acc[j] + pr.bout[c + j];
        } else {
            int q = tile - 64;
            int gi = q >> 5;
            int c0 = (q & 31) * 8;
            const float* Wg = (gi == 0) ? pr.Wmw : (gi == 1) ? pr.Wmu
                            : (gi == 2) ? pr.Wd : pr.Ws;
            const float* bg = (gi == 0) ? pr.bmw : (gi == 1) ? pr.bmu
                            : (gi == 2) ? pr.bd : pr.bs;
            gemm8(sm, g_h[1], HD, HD, g_h[1], HD, HD,
                  Wg + (size_t)(PD + c0) * HD, HD, acc);
            int c = c0 + g2;
#pragma unroll
            for (int j = 0; j < 2; j++)
                g_wg[gi][row * PD + c + j] = acc[j] + bg[PD + c + j];
        }
    }
    gridbar();

    // ---- PF2: final combine m[1] ----
    for (int tile = blockIdx.x; tile < 8; tile += NBLK) {
        int e0 = tile * 2048;
#pragma unroll
        for (int j = 0; j < 8; j++) {
            int e = e0 + tid + j * 256;
            float w = sigf(g_wg[0][e]) * sigf(g_wg[2][e] * dopa)
                      * (1.f - sigf(g_wg[3][e] * sero));
            g_m[1][e] = (1.f - w) * g_m[1][e] + w * tanhf_(g_wg[1][e]);
        }
    }
    gridbar();

    // ---- PF3: write h_final, m_final (guard by out_size) ----
    {
        long long base_h = (long long)BB * TSTEPS * OD;
        long long base_m = base_h + (long long)LNUM * BB * HD;
        const float* hp = &g_h[0][0];
        for (int i = blockIdx.x * NTHR + tid; i < LNUM * BB * HD; i += NBLK * NTHR)
            if (base_h + i < pr.out_size) pr.out[base_h + i] = hp[i];
        const float* mp = &g_m[0][0];
        for (int i = blockIdx.x * NTHR + tid; i < LNUM * BB * PD; i += NBLK * NTHR)
            if (base_m + i < pr.out_size) pr.out[base_m + i] = mp[i];
    }
}

extern "C" void kernel_launch(void* const* d_in, const int* in_sizes, int n_in,
                              void* d_out, int out_size) {
    Params p;
    p.x    = (const float*)d_in[0];
    p.Wr   = (const float*)d_in[1];
    p.br   = (const float*)d_in[2];
    p.Wu   = (const float*)d_in[3];
    p.bu   = (const float*)d_in[4];
    p.Wn   = (const float*)d_in[5];
    p.bn   = (const float*)d_in[6];
    p.Wmr  = (const float*)d_in[7];
    p.bmr  = (const float*)d_in[8];
    p.Wmw  = (const float*)d_in[9];
    p.bmw  = (const float*)d_in[10];
    p.Wmu  = (const float*)d_in[11];
    p.bmu  = (const float*)d_in[12];
    p.Wmh  = (const float*)d_in[13];
    p.bmh  = (const float*)d_in[14];
    p.Wd   = (const float*)d_in[15];
    p.bd   = (const float*)d_in[16];
    p.Ws   = (const float*)d_in[17];
    p.bs   = (const float*)d_in[18];
    p.Wout = (const float*)d_in[19];
    p.bout = (const float*)d_in[20];
    p.dop  = (const float*)d_in[21];
    p.ser  = (const float*)d_in[22];
    p.out  = (float*)d_out;
    p.out_size = (long long)out_size;
    gru_kernel<<<NBLK, NTHR>>>(p);
}